// round 3
// baseline (speedup 1.0000x reference)
#include <cuda_runtime.h>
#include <cstdint>

#define HH   128
#define WWD  128
#define HWI  (HH*WWD)
#define CIN  1024
#define CMID 512
#define NAA  9
#define NANCH (HWI*NAA)    // 147456
#define PRE  6000
#define POST 300
#define NW   94            // ceil(6000/64)
#define LOC_OFF (NANCH*2)          // 294912
#define ROI_OFF (NANCH*2 + NANCH*4) // 884736

// conv GEMM config
#define BK 16
#define KP 3072            // kh*1024+ci
#define NSLICE (KP/BK)     // 192
#define AS_STRIDE 384      // per kk: 3 kw * 128 co
#define AS_BUF (BK*AS_STRIDE)   // 6144 floats
#define BS_ROW 136
#define BS_BUF (BK*BS_ROW)      // 2176 floats
#define SM_BS  (2*AS_BUF)       // 12288
#define SM_WSH (SM_BS + 2*BS_BUF) // 16640
#define SM_FLOATS (SM_WSH + 54*128) // 23552
#define SM_BYTES (SM_FLOATS*4)      // 94208

struct Ctrl {
    unsigned b1;
    unsigned cAbove1;
    unsigned thresholdKey;
    int      candCount;
};

// ---- static device scratch (no allocations allowed) ----
__device__ __align__(16) float g_Ar2[KP*3*CMID];      // 18.9 MB weights [k'][kw][co]
__device__ __align__(16) float g_Wh[54*CMID];         // head weights [o][c]
__device__ __align__(16) float g_part[4*HWI*54];      // 14.2 MB head partials [cotile][p][o]
__device__ float4 g_boxes4[NANCH];
__device__ unsigned g_key[NANCH];
__device__ unsigned g_hist1[4096];
__device__ unsigned g_hist2[4096];
__device__ unsigned long long g_cand[8192];
__device__ float4 g_sorted[PRE];
__device__ unsigned long long g_mask[(size_t)PRE*NW];
__device__ unsigned long long g_keep[NW];
__device__ Ctrl g_ctrl;

// =====================================================================
__global__ void zero_ctrl_k() {
    int t = blockIdx.x*blockDim.x + threadIdx.x;
    if (t < 4096) { g_hist1[t] = 0; g_hist2[t] = 0; }
    if (t == 0) { g_ctrl.candCount = 0; g_ctrl.b1 = 0; g_ctrl.cAbove1 = 0; g_ctrl.thresholdKey = 0; }
}

// =====================================================================
// weight reorder: g_Ar2[(kh*1024+ci)*3 + kw][co] = Wc[co][ci][kh][kw]
// =====================================================================
__global__ void reorder2(const float* __restrict__ Wc) {
    int kp = blockIdx.x;             // 0..3071
    int kh = kp >> 10, ci = kp & 1023;
    for (int co = threadIdx.x; co < CMID; co += blockDim.x) {
        const float* s = Wc + ((size_t)co*CIN + ci)*9 + kh*3;
        float w0 = s[0], w1 = s[1], w2 = s[2];
        g_Ar2[(kp*3 + 0)*CMID + co] = w0;
        g_Ar2[(kp*3 + 1)*CMID + co] = w1;
        g_Ar2[(kp*3 + 2)*CMID + co] = w2;
    }
}

__global__ void build_wh(const float* __restrict__ Wsc, const float* __restrict__ Wlc) {
    int idx = blockIdx.x*blockDim.x + threadIdx.x;  // 54*512
    int o = idx >> 9;
    g_Wh[idx] = (o < 18) ? Wsc[idx] : Wlc[idx - 18*CMID];
}

// =====================================================================
// fused conv(3x3,1024->512)+bias+relu + 1x1 head partials
// implicit GEMM: M=512(co) x N=16384(p) x K'=3072(kh,ci), kw in registers
// tile 128co x 128w (one image row), 256 thr, 8x8/thr, cp.async dbl-buffer
// =====================================================================
__device__ __forceinline__ void cpasync16(float* dst, const float* src, int sz) {
    unsigned d = (unsigned)__cvta_generic_to_shared(dst);
    asm volatile("cp.async.cg.shared.global [%0], [%1], 16, %2;\n"
                 :: "r"(d), "l"(src), "r"(sz) : "memory");
}

__device__ __forceinline__ void load_slice(const float* __restrict__ X,
        float* As, float* Bs, int h, int coBase, int tid, int s, int buf) {
    int kh = s >> 6;                 // s/64 (16 | 1024 so kh constant per slice)
    int rowg = h + kh - 1;
    int sz  = (rowg >= 0 && rowg < HH) ? 16 : 0;
    int rowc = sz ? rowg : 0;
    float* Bb = Bs + buf*BS_BUF;
    float* Ab = As + buf*AS_BUF;
#pragma unroll
    for (int rq = 0; rq < 2; rq++) {
        int q = tid + rq*256;
        int row = q >> 5, c4 = (q & 31) << 2;
        int ci = s*BK + row - (kh << 10);
        const float* src = X + ci*HWI + rowc*WWD + c4;
        cpasync16(&Bb[row*BS_ROW + 4 + c4], src, sz);
    }
#pragma unroll
    for (int rq = 0; rq < 6; rq++) {
        int q = tid + rq*256;
        int kk = q/96, rem = q - kk*96;
        int kw = rem >> 5, c4 = (rem & 31) << 2;
        const float* src = g_Ar2 + (((s*BK + kk)*3 + kw) << 9) + coBase + c4;
        cpasync16(&Ab[kk*AS_STRIDE + (kw << 7) + c4], src, 16);
    }
    asm volatile("cp.async.commit_group;" ::: "memory");
}

__global__ void __launch_bounds__(256, 2)
conv_fused(const float* __restrict__ X, const float* __restrict__ bconv) {
    extern __shared__ float sm[];
    float* As  = sm;             // [2][16][3][128]
    float* Bs  = sm + SM_BS;     // [2][16][136]
    float* Wsh = sm + SM_WSH;    // [54][128]
    int h = blockIdx.x, coBase = blockIdx.y << 7;
    int tid = threadIdx.x;
    int ty = tid >> 4, tx = tid & 15;

    // stage head-weight slice for this co-tile
    for (int idx = tid; idx < 54*128; idx += 256)
        Wsh[idx] = g_Wh[(idx >> 7)*CMID + coBase + (idx & 127)];
    // zero Bs halo pads (never touched by cp.async)
    {
        int buf = tid >> 7, r = (tid >> 3) & 15, pz = tid & 7;
        int idx = (pz < 4) ? pz : 128 + pz;
        Bs[buf*BS_BUF + r*BS_ROW + idx] = 0.f;
    }

    float c[8][8];
#pragma unroll
    for (int i = 0; i < 8; i++)
#pragma unroll
        for (int j = 0; j < 8; j++) c[i][j] = 0.f;

    load_slice(X, As, Bs, h, coBase, tid, 0, 0);

    for (int s = 0; s < NSLICE; s++) {
        int buf = s & 1;
        if (s + 1 < NSLICE) {
            load_slice(X, As, Bs, h, coBase, tid, s + 1, buf ^ 1);
            asm volatile("cp.async.wait_group 1;" ::: "memory");
        } else {
            asm volatile("cp.async.wait_group 0;" ::: "memory");
        }
        __syncthreads();
        const float* Ab = As + buf*AS_BUF;
        const float* Bb = Bs + buf*BS_BUF;
#pragma unroll 4
        for (int kk = 0; kk < BK; kk++) {
            float b[16], a0[8], a1[8], a2[8];
            const float* br = Bb + kk*BS_ROW + tx*8;
            *(float4*)(b)      = *(const float4*)(br);
            *(float4*)(b + 4)  = *(const float4*)(br + 4);
            *(float4*)(b + 8)  = *(const float4*)(br + 8);
            *(float4*)(b + 12) = *(const float4*)(br + 12);
            const float* ar = Ab + kk*AS_STRIDE + ty*8;
            *(float4*)(a0)     = *(const float4*)(ar);
            *(float4*)(a0 + 4) = *(const float4*)(ar + 4);
            *(float4*)(a1)     = *(const float4*)(ar + 128);
            *(float4*)(a1 + 4) = *(const float4*)(ar + 132);
            *(float4*)(a2)     = *(const float4*)(ar + 256);
            *(float4*)(a2 + 4) = *(const float4*)(ar + 260);
#pragma unroll
            for (int i = 0; i < 8; i++)
#pragma unroll
                for (int j = 0; j < 8; j++) {
                    c[i][j] = fmaf(a0[i], b[j + 3], c[i][j]);
                    c[i][j] = fmaf(a1[i], b[j + 4], c[i][j]);
                    c[i][j] = fmaf(a2[i], b[j + 5], c[i][j]);
                }
        }
        __syncthreads();
    }

    // ---- epilogue: bias+relu -> shared feat tile (aliases buffers) ----
    float* Sfeat = sm;   // [128co][128p], Wsh region untouched
#pragma unroll
    for (int i = 0; i < 8; i++) {
        int co = ty*8 + i;
        float bb = bconv[coBase + co];
        float4 v0 = make_float4(fmaxf(c[i][0]+bb,0.f), fmaxf(c[i][1]+bb,0.f),
                                fmaxf(c[i][2]+bb,0.f), fmaxf(c[i][3]+bb,0.f));
        float4 v1 = make_float4(fmaxf(c[i][4]+bb,0.f), fmaxf(c[i][5]+bb,0.f),
                                fmaxf(c[i][6]+bb,0.f), fmaxf(c[i][7]+bb,0.f));
        *(float4*)&Sfeat[co*128 + tx*8]     = v0;
        *(float4*)&Sfeat[co*128 + tx*8 + 4] = v1;
    }
    __syncthreads();

    // ---- head partials: 54 outs x 128 p over this co-tile's 128 channels ----
    int p = tid & 127, oHalf = tid >> 7;
    float acc[27];
#pragma unroll
    for (int i = 0; i < 27; i++) acc[i] = 0.f;
    const float* Wrow = Wsh + oHalf*27*128;
    for (int co = 0; co < 128; co++) {
        float f = Sfeat[co*128 + p];
#pragma unroll
        for (int i = 0; i < 27; i++)
            acc[i] = fmaf(f, Wrow[i*128 + co], acc[i]);
    }
    float* dst = g_part + ((size_t)(blockIdx.y*HWI + h*WWD + p))*54 + oHalf*27;
#pragma unroll
    for (int i = 0; i < 27; i++) dst[i] = acc[i];
}

// =====================================================================
// per-anchor: reduce head partials, write score/loc outputs, softmax fg,
// loc2bbox, clip, min-size filter, key + hist1
// =====================================================================
__global__ void prep_k(const float* __restrict__ anch,
                       const int* __restrict__ img, const float* __restrict__ scale,
                       const float* __restrict__ bsc, const float* __restrict__ blc,
                       float* __restrict__ out) {
    __shared__ unsigned sh[4096];
    for (int i = threadIdx.x; i < 4096; i += blockDim.x) sh[i] = 0;
    __syncthreads();
    int i = blockIdx.x*blockDim.x + threadIdx.x;   // exactly NANCH threads
    {
        int p = i / 9, a = i - p*9;
        float s0 = bsc[2*a], s1 = bsc[2*a + 1];
        float dy = blc[4*a], dx = blc[4*a+1], dh = blc[4*a+2], dw = blc[4*a+3];
#pragma unroll
        for (int t = 0; t < 4; t++) {
            const float* pp = g_part + ((size_t)(t*HWI + p))*54;
            s0 += pp[2*a];      s1 += pp[2*a + 1];
            dy += pp[18 + 4*a]; dx += pp[18 + 4*a + 1];
            dh += pp[18 + 4*a + 2]; dw += pp[18 + 4*a + 3];
        }
        out[p*18 + 2*a]     = s0;
        out[p*18 + 2*a + 1] = s1;
        float* lo = out + LOC_OFF + p*36 + 4*a;
        lo[0] = dy; lo[1] = dx; lo[2] = dh; lo[3] = dw;

        float m = fmaxf(s0, s1);
        float e0 = expf(s0 - m), e1 = expf(s1 - m);
        float fg = e1 / (e0 + e1);
        float ay1 = anch[i*4], ax1 = anch[i*4+1], ay2 = anch[i*4+2], ax2 = anch[i*4+3];
        float ahh = ay2 - ay1, aww = ax2 - ax1;
        float acy = ay1 + 0.5f*ahh, acx = ax1 + 0.5f*aww;
        float cy = dy*ahh + acy, cx = dx*aww + acx;
        float bh = expf(dh)*ahh, bw = expf(dw)*aww;
        float imh = (float)img[0], imw = (float)img[1];
        float y1 = fminf(fmaxf(cy - 0.5f*bh, 0.f), imh);
        float x1 = fminf(fmaxf(cx - 0.5f*bw, 0.f), imw);
        float y2 = fminf(fmaxf(cy + 0.5f*bh, 0.f), imh);
        float x2 = fminf(fmaxf(cx + 0.5f*bw, 0.f), imw);
        g_boxes4[i] = make_float4(y1, x1, y2, x2);
        float ms = 16.0f * scale[0];
        bool valid = ((y2 - y1) >= ms) && ((x2 - x1) >= ms);
        float sc = valid ? fg : -1e9f;
        unsigned u = __float_as_uint(sc);
        u = (u & 0x80000000u) ? ~u : (u | 0x80000000u);
        g_key[i] = u;
        atomicAdd(&sh[u >> 20], 1u);
    }
    __syncthreads();
    for (int b = threadIdx.x; b < 4096; b += blockDim.x)
        if (sh[b]) atomicAdd(&g_hist1[b], sh[b]);
}

// =====================================================================
// radix-threshold selection (two 12-bit levels)
// =====================================================================
__global__ void scan1_k() {
    __shared__ unsigned seg[32];
    int t = threadIdx.x;
    unsigned s = 0;
    for (int b = 0; b < 128; b++) s += g_hist1[t*128 + b];
    seg[t] = s;
    __syncwarp();
    if (t == 0) {
        unsigned target = PRE, cum = 0; int si = 31;
        for (; si >= 0; si--) { if (cum + seg[si] >= target) break; cum += seg[si]; }
        if (si < 0) si = 0;
        unsigned c2 = cum; unsigned b1 = si*128;
        for (int b = si*128 + 127; b >= si*128; b--) {
            unsigned hv = g_hist1[b];
            if (c2 + hv >= target) { b1 = b; break; }
            c2 += hv;
        }
        g_ctrl.b1 = b1; g_ctrl.cAbove1 = c2;
    }
}

__global__ void hist2_k() {
    int i = blockIdx.x*blockDim.x + threadIdx.x;
    unsigned u = g_key[i];
    if ((u >> 20) == g_ctrl.b1) atomicAdd(&g_hist2[(u >> 8) & 0xFFFu], 1u);
}

__global__ void scan2_k() {
    __shared__ unsigned seg[32];
    int t = threadIdx.x;
    unsigned s = 0;
    for (int b = 0; b < 128; b++) s += g_hist2[t*128 + b];
    seg[t] = s;
    __syncwarp();
    if (t == 0) {
        unsigned target = PRE - g_ctrl.cAbove1, cum = 0; int si = 31;
        for (; si >= 0; si--) { if (cum + seg[si] >= target) break; cum += seg[si]; }
        if (si < 0) si = 0;
        unsigned c2 = cum; unsigned b2 = si*128;
        for (int b = si*128 + 127; b >= si*128; b--) {
            unsigned hv = g_hist2[b];
            if (c2 + hv >= target) { b2 = b; break; }
            c2 += hv;
        }
        g_ctrl.thresholdKey = (g_ctrl.b1 << 20) | (b2 << 8);
    }
}

__global__ void compact_k() {
    int i = blockIdx.x*blockDim.x + threadIdx.x;
    unsigned u = g_key[i];
    if (u >= g_ctrl.thresholdKey) {
        int pos = atomicAdd(&g_ctrl.candCount, 1);
        if (pos < 8192)
            g_cand[pos] = ((unsigned long long)(~u) << 32) | (unsigned)i;
    }
}

// =====================================================================
// single-block bitonic sort (score desc, index asc) -> exact lax.top_k order
// =====================================================================
__global__ void bitonic_k() {
    extern __shared__ unsigned long long shm[];
    int tid = threadIdx.x;
    int n = g_ctrl.candCount; if (n > 8192) n = 8192;
    for (int i = tid; i < 8192; i += 1024)
        shm[i] = (i < n) ? g_cand[i] : 0xFFFFFFFFFFFFFFFFull;
    __syncthreads();
    for (int k = 2; k <= 8192; k <<= 1) {
        for (int j = k >> 1; j > 0; j >>= 1) {
            for (int e = tid; e < 8192; e += 1024) {
                int p = e ^ j;
                if (p > e) {
                    unsigned long long a = shm[e], b = shm[p];
                    bool up = ((e & k) == 0);
                    if (up ? (a > b) : (a < b)) { shm[e] = b; shm[p] = a; }
                }
            }
            __syncthreads();
        }
    }
    for (int r = tid; r < PRE; r += 1024) {
        unsigned idx = (unsigned)shm[r];
        g_sorted[r] = g_boxes4[idx];
    }
}

// =====================================================================
// IoU suppression bitmask
// =====================================================================
__global__ void mask_k() {
    int bx = blockIdx.x, by = blockIdx.y;
    if (bx < by) return;
    __shared__ float4 cb[64];
    int t = threadIdx.x;
    int j0 = bx * 64;
    {
        int j = j0 + t;
        cb[t] = (j < PRE) ? g_sorted[j] : make_float4(0, 0, 0, 0);
    }
    __syncthreads();
    int i = by*64 + t;
    if (i >= PRE) return;
    float4 bi = g_sorted[i];
    float areai = (bi.z - bi.x)*(bi.w - bi.y);
    unsigned long long word = 0;
#pragma unroll 4
    for (int jj = 0; jj < 64; jj++) {
        int j = j0 + jj;
        if (j > i && j < PRE) {
            float4 bj = cb[jj];
            float tly = fmaxf(bi.x, bj.x), tlx = fmaxf(bi.y, bj.y);
            float bry = fminf(bi.z, bj.z), brx = fminf(bi.w, bj.w);
            float hv = fmaxf(bry - tly, 0.f), wv = fmaxf(brx - tlx, 0.f);
            float inter = hv * wv;
            float areaj = (bj.z - bj.x)*(bj.w - bj.y);
            float iou = inter / (areai + areaj - inter + 1e-9f);
            if (iou > 0.7f) word |= (1ull << jj);
        }
    }
    g_mask[(size_t)i*NW + bx] = word;
}

// =====================================================================
// exact serial-greedy NMS reduce
// =====================================================================
__global__ void nms_reduce_k() {
    __shared__ unsigned long long removed[NW];
    __shared__ unsigned long long kbSh;
    int tid = threadIdx.x;
    for (int i = tid; i < NW; i += blockDim.x) removed[i] = 0;
    __syncthreads();
    for (int c = 0; c < NW; c++) {
        if (tid < 32) {
            int ra = c*64 + tid, rb = ra + 32;
            unsigned long long ia = (ra < PRE) ? g_mask[(size_t)ra*NW + c] : 0ull;
            unsigned long long ib = (rb < PRE) ? g_mask[(size_t)rb*NW + c] : 0ull;
            unsigned long long rw = removed[c];
            unsigned long long kb = 0;
#pragma unroll
            for (int k = 0; k < 32; k++) {
                unsigned long long mk = __shfl_sync(0xffffffffu, ia, k);
                if ((c*64 + k) < PRE && !((rw >> k) & 1ull)) { kb |= (1ull << k); rw |= mk; }
            }
#pragma unroll
            for (int k = 0; k < 32; k++) {
                unsigned long long mk = __shfl_sync(0xffffffffu, ib, k);
                int k2 = k + 32;
                if ((c*64 + k2) < PRE && !((rw >> k2) & 1ull)) { kb |= (1ull << k2); rw |= mk; }
            }
            if (tid == 0) { kbSh = kb; g_keep[c] = kb; }
        }
        __syncthreads();
        unsigned long long kb = kbSh;
        int slots = (NW - 1 - c) * 2;
        for (int slot = tid; slot < slots; slot += blockDim.x) {
            int w  = c + 1 + (slot >> 1);
            int k0 = (slot & 1) * 32;
            unsigned hk = (unsigned)(kb >> k0);
            unsigned long long acc = 0;
            while (hk) {
                int k = __ffs(hk) - 1; hk &= hk - 1;
                acc |= g_mask[(size_t)(c*64 + k0 + k)*NW + w];
            }
            if (acc) atomicOr(&removed[w], acc);
        }
        __syncthreads();
    }
}

// =====================================================================
__global__ void rois_k(float* __restrict__ out) {
    __shared__ int list[POST];
    __shared__ int nkS;
    if (threadIdx.x == 0) {
        int nk = 0;
        for (int w = 0; w < NW && nk < POST; w++) {
            unsigned long long bits = g_keep[w];
            while (bits && nk < POST) {
                int k = __ffsll(bits) - 1; bits &= bits - 1;
                list[nk++] = w*64 + k;
            }
        }
        nkS = nk;
    }
    __syncthreads();
    int nk = nkS;
    for (int r = threadIdx.x; r < POST; r += blockDim.x) {
        float4 v = make_float4(0, 0, 0, 0);
        if (r < nk) v = g_sorted[list[r]];
        *(float4*)(out + ROI_OFF + r*4) = v;
    }
}

// =====================================================================
extern "C" void kernel_launch(void* const* d_in, const int* in_sizes, int n_in,
                              void* d_out, int out_size) {
    const float* x     = (const float*)d_in[0];
    const float* anch  = (const float*)d_in[1];
    const int*   img   = (const int*)  d_in[2];
    const float* scale = (const float*)d_in[3];
    const float* Wc    = (const float*)d_in[4];
    const float* bc    = (const float*)d_in[5];
    const float* Wsc   = (const float*)d_in[6];
    const float* bsc   = (const float*)d_in[7];
    const float* Wlc   = (const float*)d_in[8];
    const float* blc   = (const float*)d_in[9];
    float* out = (float*)d_out;

    zero_ctrl_k<<<16, 256>>>();
    reorder2<<<KP, 128>>>(Wc);
    build_wh<<<54, 512>>>(Wsc, Wlc);
    cudaFuncSetAttribute(conv_fused, cudaFuncAttributeMaxDynamicSharedMemorySize, SM_BYTES);
    conv_fused<<<dim3(HH, 4), 256, SM_BYTES>>>(x, bc);
    prep_k<<<NANCH/256, 256>>>(anch, img, scale, bsc, blc, out);
    scan1_k<<<1, 32>>>();
    hist2_k<<<NANCH/256, 256>>>();
    scan2_k<<<1, 32>>>();
    compact_k<<<NANCH/256, 256>>>();
    cudaFuncSetAttribute(bitonic_k, cudaFuncAttributeMaxDynamicSharedMemorySize, 8192*8);
    bitonic_k<<<1, 1024, 8192*8>>>();
    mask_k<<<dim3(NW, NW), 64>>>();
    nms_reduce_k<<<1, 256>>>();
    rois_k<<<1, 256>>>(out);
}

// round 6
// speedup vs baseline: 1.0887x; 1.0887x over previous
#include <cuda_runtime.h>
#include <cstdint>

#define HH   128
#define WWD  128
#define HWI  (HH*WWD)
#define CIN  1024
#define CMID 512
#define KTOT 9216
#define NANCH (HWI*9)      // 147456
#define PRE  6000
#define POST 300
#define NW   94
#define LOC_OFF (NANCH*2)
#define ROI_OFF (NANCH*6)

// conv_tc smem layout (float offsets)
#define XS_F    0           // X tile: 2 mats x [4 rows][130 wcol][pad20] = 2*10400
#define XS_MAT  10400
#define BS_F    20800       // B: 3 bufs x (2 mats x 64co x pad20)
#define BS_BUFF 2560
#define BS_MAT  1280
#define WSH_F   28480       // 54 x 64
#define BIAS_F  31936       // 64
#define SM_FLOATS 32000
#define SM_BYTES  (SM_FLOATS*4)   // 128000

struct Ctrl { unsigned b1, cAbove1, thresholdKey; int candCount; };

// ---- static device scratch ----
__device__ __align__(16) float g_Xhi[CIN*HWI];   // channel-last [p][ci]
__device__ __align__(16) float g_Xlo[CIN*HWI];
__device__ __align__(16) float g_Whi[CMID*KTOT]; // [co][k], k=(kh*3+kw)*1024+ci
__device__ __align__(16) float g_Wlo[CMID*KTOT];
__device__ __align__(16) float g_Wh[54*CMID];
__device__ __align__(16) float g_part[8*HWI*54]; // [cotile][p][o]
__device__ float4 g_boxes4[NANCH];
__device__ unsigned g_key[NANCH];
__device__ unsigned g_hist1[4096];
__device__ unsigned g_hist2[4096];
__device__ unsigned long long g_cand[8192];
__device__ float4 g_sorted[PRE];
__device__ unsigned long long g_mask[(size_t)PRE*NW];
__device__ unsigned long long g_keep[NW];
__device__ Ctrl g_ctrl;

// ================= helpers =================
__device__ __forceinline__ void cpasync16(float* dst, const float* src, int sz) {
    unsigned d = (unsigned)__cvta_generic_to_shared(dst);
    asm volatile("cp.async.cg.shared.global [%0], [%1], 16, %2;\n"
                 :: "r"(d), "l"(src), "r"(sz) : "memory");
}
__device__ __forceinline__ void mma8(float* c, const uint32_t* a, const uint32_t* b) {
    asm volatile("mma.sync.aligned.m16n8k8.row.col.f32.tf32.tf32.f32 "
        "{%0,%1,%2,%3}, {%4,%5,%6,%7}, {%8,%9}, {%0,%1,%2,%3};"
        : "+f"(c[0]), "+f"(c[1]), "+f"(c[2]), "+f"(c[3])
        : "r"(a[0]), "r"(a[1]), "r"(a[2]), "r"(a[3]), "r"(b[0]), "r"(b[1]));
}
__device__ __forceinline__ void tf32_split(float x, float& hi, float& lo) {
    uint32_t hb, lb;
    asm("cvt.rna.tf32.f32 %0, %1;" : "=r"(hb) : "f"(x));
    hi = __uint_as_float(hb);
    float r = x - hi;
    asm("cvt.rna.tf32.f32 %0, %1;" : "=r"(lb) : "f"(r));
    lo = __uint_as_float(lb);
}

// ================= prep kernels =================
__global__ void zero_ctrl_k() {
    int t = blockIdx.x*blockDim.x + threadIdx.x;
    if (t < 4096) { g_hist1[t] = 0; g_hist2[t] = 0; }
    if (t == 0) { g_ctrl.candCount = 0; g_ctrl.b1 = 0; g_ctrl.cAbove1 = 0; g_ctrl.thresholdKey = 0; }
}

// X [ci][h][w] -> channel-last hi/lo [p][ci]
__global__ void split_x_k(const float* __restrict__ X) {
    __shared__ float t[32][33];
    int h = blockIdx.x, w0 = blockIdx.y << 5, c0 = blockIdx.z << 5;
    int tid = threadIdx.x;
#pragma unroll
    for (int it = 0; it < 4; it++) {
        int idx = tid + it*256;
        int ci = idx >> 5, w = idx & 31;
        t[ci][w] = X[(c0 + ci)*HWI + h*WWD + w0 + w];
    }
    __syncthreads();
#pragma unroll
    for (int it = 0; it < 4; it++) {
        int idx = tid + it*256;
        int w = idx >> 5, ci = idx & 31;
        float hi, lo;
        tf32_split(t[ci][w], hi, lo);
        size_t off = ((size_t)(h*WWD + w0 + w) << 10) + c0 + ci;
        g_Xhi[off] = hi; g_Xlo[off] = lo;
    }
}

// W [co][ci][3][3] -> hi/lo [co][k], k=(kh*3+kw)*1024+ci
__global__ void split_w_k(const float* __restrict__ Wc) {
    int co = blockIdx.x;
    for (int k = threadIdx.x; k < KTOT; k += blockDim.x) {
        int g = k >> 10, ci = k & 1023;
        float v = Wc[((size_t)co*CIN + ci)*9 + g];
        float hi, lo;
        tf32_split(v, hi, lo);
        g_Whi[(size_t)co*KTOT + k] = hi;
        g_Wlo[(size_t)co*KTOT + k] = lo;
    }
}

__global__ void build_wh(const float* __restrict__ Wsc, const float* __restrict__ Wlc) {
    int idx = blockIdx.x*blockDim.x + threadIdx.x;  // 54*512
    int o = idx >> 9;
    g_Wh[idx] = (o < 18) ? Wsc[idx] : Wlc[idx - 18*CMID];
}

// =====================================================================
// conv 3x3 1024->512 via mma.sync tf32, 3-term split, RZ-safe accumulation:
//   acc_hh (MMA, hi*hi, flushed to fp32 acc_sum every ci-chunk)
//   acc_x  (MMA, hi*lo + lo*hi, stays small)
// CTA: 256 pos (2 rows) x 64 co; 8 warps (4m x 2n), warp tile 64x32
// =====================================================================
__global__ void __launch_bounds__(256, 1)
conv_tc(const float* __restrict__ bconv) {
    extern __shared__ float sm[];
    float* Xs = sm + XS_F;
    float* Bs = sm + BS_F;
    float* Wsh = sm + WSH_F;
    float* bias_sh = sm + BIAS_F;
    const int tid = threadIdx.x, lane = tid & 31, wid = tid >> 5;
    const int g8 = lane >> 2, t4 = lane & 3;
    const int wm = wid & 3, wn = wid >> 2;     // warp grid 4(m) x 2(n)
    const int bt = blockIdx.x, coTile = blockIdx.y;
    const int coBase = coTile << 6;
    const int hBase = bt << 1;

    for (int i = tid; i < 54*64; i += 256)
        Wsh[i] = g_Wh[(i >> 6)*CMID + coBase + (i & 63)];
    if (tid < 64) bias_sh[tid] = bconv[coBase + tid];

    // per-thread fragment base addresses (floats)
    int bA[4];
#pragma unroll
    for (int mi = 0; mi < 4; mi++) {
        int p0 = wm*64 + mi*16 + g8;
        bA[mi] = (p0 >> 7)*2600 + (p0 & 127)*20 + t4;
    }
    int bB[4];
#pragma unroll
    for (int ni = 0; ni < 4; ni++)
        bB[ni] = (wn*32 + ni*8 + g8)*20 + t4;

    float acc_hh[4][4][4], acc_x[4][4][4], acc_sum[4][4][4];
#pragma unroll
    for (int mi = 0; mi < 4; mi++)
#pragma unroll
        for (int ni = 0; ni < 4; ni++)
#pragma unroll
            for (int q = 0; q < 4; q++) {
                acc_hh[mi][ni][q] = 0.f; acc_x[mi][ni][q] = 0.f; acc_sum[mi][ni][q] = 0.f;
            }

    for (int ch = 0; ch < 64; ch++) {
        const int ci0 = ch << 4;
        __syncthreads();    // Xs + all B bufs free
        // ---- stage X tile: 2 mats x 4 rows x 130 wcols x 16 ci ----
        for (int idx = tid; idx < 4160; idx += 256) {
            int seg = idx & 3, s2 = idx >> 2;
            int mat = (s2 >= 520) ? 1 : 0;
            int rem = s2 - mat*520;
            int row = rem / 130, wc = rem - row*130;
            int hp = hBase + row - 1, wp = wc - 1;
            bool ok = ((unsigned)hp < 128u) && ((unsigned)wp < 128u);
            const float* src = (mat ? g_Xlo : g_Xhi)
                + (((size_t)((hp & 127)*WWD + (wp & 127))) << 10) + ci0 + (seg << 2);
            cpasync16(Xs + mat*XS_MAT + row*2600 + wc*20 + (seg << 2), src, ok ? 16 : 0);
        }
        asm volatile("cp.async.commit_group;" ::: "memory");
        // ---- stage B for tap g=0 (buf 0): 2 mats x 64 co x 4 segs ----
        {
#pragma unroll
            for (int q = 0; q < 2; q++) {
                int idx = tid + (q << 8);
                int mat = idx >> 8, co = (idx >> 2) & 63, seg = idx & 3;
                const float* src = (mat ? g_Wlo : g_Whi)
                    + (size_t)(coBase + co)*KTOT + ci0 + (seg << 2);
                cpasync16(Bs + mat*BS_MAT + co*20 + (seg << 2), src, 16);
            }
            asm volatile("cp.async.commit_group;" ::: "memory");
        }

        for (int g = 0; g < 9; g++) {
            if (g + 1 < 9) {       // stage next tap into buf (g+1)%3
                int nb = (g + 1) % 3;
#pragma unroll
                for (int q = 0; q < 2; q++) {
                    int idx = tid + (q << 8);
                    int mat = idx >> 8, co = (idx >> 2) & 63, seg = idx & 3;
                    const float* src = (mat ? g_Wlo : g_Whi)
                        + (size_t)(coBase + co)*KTOT + ((g + 1) << 10) + ci0 + (seg << 2);
                    cpasync16(Bs + nb*BS_BUFF + mat*BS_MAT + co*20 + (seg << 2), src, 16);
                }
                asm volatile("cp.async.commit_group;" ::: "memory");
                asm volatile("cp.async.wait_group 1;" ::: "memory");
            } else {
                asm volatile("cp.async.wait_group 0;" ::: "memory");
            }
            __syncthreads();

            const int kh = g / 3, kw = g - kh*3;
            const int aoff = kh*2600 + kw*20;
            const float* Bb = Bs + (g % 3)*BS_BUFF;
#pragma unroll
            for (int ks = 0; ks < 16; ks += 8) {
                uint32_t bh[4][2], bl[4][2];
#pragma unroll
                for (int ni = 0; ni < 4; ni++) {
                    bh[ni][0] = __float_as_uint(Bb[bB[ni] + ks]);
                    bh[ni][1] = __float_as_uint(Bb[bB[ni] + ks + 4]);
                    bl[ni][0] = __float_as_uint(Bb[BS_MAT + bB[ni] + ks]);
                    bl[ni][1] = __float_as_uint(Bb[BS_MAT + bB[ni] + ks + 4]);
                }
#pragma unroll
                for (int mi = 0; mi < 4; mi++) {
                    int ab = bA[mi] + aoff + ks;
                    uint32_t ah[4], al[4];
                    ah[0] = __float_as_uint(Xs[ab]);
                    ah[1] = __float_as_uint(Xs[ab + 160]);
                    ah[2] = __float_as_uint(Xs[ab + 4]);
                    ah[3] = __float_as_uint(Xs[ab + 164]);
                    al[0] = __float_as_uint(Xs[XS_MAT + ab]);
                    al[1] = __float_as_uint(Xs[XS_MAT + ab + 160]);
                    al[2] = __float_as_uint(Xs[XS_MAT + ab + 4]);
                    al[3] = __float_as_uint(Xs[XS_MAT + ab + 164]);
#pragma unroll
                    for (int ni = 0; ni < 4; ni++) {
                        mma8(acc_hh[mi][ni], ah, bh[ni]);
                        mma8(acc_x[mi][ni], ah, bl[ni]);
                        mma8(acc_x[mi][ni], al, bh[ni]);
                    }
                }
            }
        }
        // ---- flush hi*hi window into RN fp32 accumulator ----
#pragma unroll
        for (int mi = 0; mi < 4; mi++)
#pragma unroll
            for (int ni = 0; ni < 4; ni++)
#pragma unroll
                for (int q = 0; q < 4; q++) {
                    acc_sum[mi][ni][q] += acc_hh[mi][ni][q];
                    acc_hh[mi][ni][q] = 0.f;
                }
    }
    __syncthreads();

    // ---- epilogue: feat tile (64co x 256p) in smem, aliases Xs ----
    float* Sfeat = Xs;   // [64][260]
#pragma unroll
    for (int mi = 0; mi < 4; mi++) {
        int p0 = wm*64 + mi*16 + g8;
#pragma unroll
        for (int ni = 0; ni < 4; ni++) {
            int co = wn*32 + ni*8 + (t4 << 1);
            float v0 = acc_sum[mi][ni][0] + acc_x[mi][ni][0] + bias_sh[co];
            float v1 = acc_sum[mi][ni][1] + acc_x[mi][ni][1] + bias_sh[co + 1];
            float v2 = acc_sum[mi][ni][2] + acc_x[mi][ni][2] + bias_sh[co];
            float v3 = acc_sum[mi][ni][3] + acc_x[mi][ni][3] + bias_sh[co + 1];
            Sfeat[co*260 + p0]           = fmaxf(v0, 0.f);
            Sfeat[(co + 1)*260 + p0]     = fmaxf(v1, 0.f);
            Sfeat[co*260 + p0 + 8]       = fmaxf(v2, 0.f);
            Sfeat[(co + 1)*260 + p0 + 8] = fmaxf(v3, 0.f);
        }
    }
    __syncthreads();

    // ---- head partials: 54 outs over this co-tile's 64 channels ----
    {
        int pl = tid;
        float a54[54];
#pragma unroll
        for (int o = 0; o < 54; o++) a54[o] = 0.f;
        for (int co = 0; co < 64; co++) {
            float f = Sfeat[co*260 + pl];
#pragma unroll
            for (int o = 0; o < 54; o++)
                a54[o] = fmaf(f, Wsh[o*64 + co], a54[o]);
        }
        float* dst = g_part + ((size_t)coTile*HWI + bt*256 + pl)*54;
#pragma unroll
        for (int o = 0; o < 54; o++) dst[o] = a54[o];
    }
}

// ================= proposal pipeline (exact) =================
__global__ void prep_k(const float* __restrict__ anch,
                       const int* __restrict__ img, const float* __restrict__ scale,
                       const float* __restrict__ bsc, const float* __restrict__ blc,
                       float* __restrict__ out) {
    __shared__ unsigned sh[4096];
    for (int i = threadIdx.x; i < 4096; i += blockDim.x) sh[i] = 0;
    __syncthreads();
    int i = blockIdx.x*blockDim.x + threadIdx.x;
    {
        int p = i / 9, a = i - p*9;
        float s0 = bsc[2*a], s1 = bsc[2*a + 1];
        float dy = blc[4*a], dx = blc[4*a+1], dh = blc[4*a+2], dw = blc[4*a+3];
#pragma unroll
        for (int t = 0; t < 8; t++) {
            const float* pp = g_part + ((size_t)t*HWI + p)*54;
            s0 += pp[2*a];      s1 += pp[2*a + 1];
            dy += pp[18 + 4*a]; dx += pp[18 + 4*a + 1];
            dh += pp[18 + 4*a + 2]; dw += pp[18 + 4*a + 3];
        }
        out[p*18 + 2*a]     = s0;
        out[p*18 + 2*a + 1] = s1;
        float* lo = out + LOC_OFF + p*36 + 4*a;
        lo[0] = dy; lo[1] = dx; lo[2] = dh; lo[3] = dw;

        float m = fmaxf(s0, s1);
        float e0 = expf(s0 - m), e1 = expf(s1 - m);
        float fg = e1 / (e0 + e1);
        float ay1 = anch[i*4], ax1 = anch[i*4+1], ay2 = anch[i*4+2], ax2 = anch[i*4+3];
        float ahh = ay2 - ay1, aww = ax2 - ax1;
        float acy = ay1 + 0.5f*ahh, acx = ax1 + 0.5f*aww;
        float cy = dy*ahh + acy, cx = dx*aww + acx;
        float bh = expf(dh)*ahh, bw = expf(dw)*aww;
        float imh = (float)img[0], imw = (float)img[1];
        float y1 = fminf(fmaxf(cy - 0.5f*bh, 0.f), imh);
        float x1 = fminf(fmaxf(cx - 0.5f*bw, 0.f), imw);
        float y2 = fminf(fmaxf(cy + 0.5f*bh, 0.f), imh);
        float x2 = fminf(fmaxf(cx + 0.5f*bw, 0.f), imw);
        g_boxes4[i] = make_float4(y1, x1, y2, x2);
        float ms = 16.0f * scale[0];
        bool valid = ((y2 - y1) >= ms) && ((x2 - x1) >= ms);
        float sc = valid ? fg : -1e9f;
        unsigned u = __float_as_uint(sc);
        u = (u & 0x80000000u) ? ~u : (u | 0x80000000u);
        g_key[i] = u;
        atomicAdd(&sh[u >> 20], 1u);
    }
    __syncthreads();
    for (int b = threadIdx.x; b < 4096; b += blockDim.x)
        if (sh[b]) atomicAdd(&g_hist1[b], sh[b]);
}

__global__ void scan1_k() {
    __shared__ unsigned seg[32];
    int t = threadIdx.x;
    unsigned s = 0;
    for (int b = 0; b < 128; b++) s += g_hist1[t*128 + b];
    seg[t] = s;
    __syncwarp();
    if (t == 0) {
        unsigned target = PRE, cum = 0; int si = 31;
        for (; si >= 0; si--) { if (cum + seg[si] >= target) break; cum += seg[si]; }
        if (si < 0) si = 0;
        unsigned c2 = cum; unsigned b1 = si*128;
        for (int b = si*128 + 127; b >= si*128; b--) {
            unsigned hv = g_hist1[b];
            if (c2 + hv >= target) { b1 = b; break; }
            c2 += hv;
        }
        g_ctrl.b1 = b1; g_ctrl.cAbove1 = c2;
    }
}

__global__ void hist2_k() {
    int i = blockIdx.x*blockDim.x + threadIdx.x;
    unsigned u = g_key[i];
    if ((u >> 20) == g_ctrl.b1) atomicAdd(&g_hist2[(u >> 8) & 0xFFFu], 1u);
}

__global__ void scan2_k() {
    __shared__ unsigned seg[32];
    int t = threadIdx.x;
    unsigned s = 0;
    for (int b = 0; b < 128; b++) s += g_hist2[t*128 + b];
    seg[t] = s;
    __syncwarp();
    if (t == 0) {
        unsigned target = PRE - g_ctrl.cAbove1, cum = 0; int si = 31;
        for (; si >= 0; si--) { if (cum + seg[si] >= target) break; cum += seg[si]; }
        if (si < 0) si = 0;
        unsigned c2 = cum; unsigned b2 = si*128;
        for (int b = si*128 + 127; b >= si*128; b--) {
            unsigned hv = g_hist2[b];
            if (c2 + hv >= target) { b2 = b; break; }
            c2 += hv;
        }
        g_ctrl.thresholdKey = (g_ctrl.b1 << 20) | (b2 << 8);
    }
}

__global__ void compact_k() {
    int i = blockIdx.x*blockDim.x + threadIdx.x;
    unsigned u = g_key[i];
    if (u >= g_ctrl.thresholdKey) {
        int pos = atomicAdd(&g_ctrl.candCount, 1);
        if (pos < 8192)
            g_cand[pos] = ((unsigned long long)(~u) << 32) | (unsigned)i;
    }
}

__global__ void bitonic_k() {
    extern __shared__ unsigned long long shm[];
    int tid = threadIdx.x;
    int n = g_ctrl.candCount; if (n > 8192) n = 8192;
    for (int i = tid; i < 8192; i += 1024)
        shm[i] = (i < n) ? g_cand[i] : 0xFFFFFFFFFFFFFFFFull;
    __syncthreads();
    for (int k = 2; k <= 8192; k <<= 1) {
        for (int j = k >> 1; j > 0; j >>= 1) {
            for (int e = tid; e < 8192; e += 1024) {
                int p = e ^ j;
                if (p > e) {
                    unsigned long long a = shm[e], b = shm[p];
                    bool up = ((e & k) == 0);
                    if (up ? (a > b) : (a < b)) { shm[e] = b; shm[p] = a; }
                }
            }
            __syncthreads();
        }
    }
    for (int r = tid; r < PRE; r += 1024) {
        unsigned idx = (unsigned)shm[r];
        g_sorted[r] = g_boxes4[idx];
    }
}

__global__ void mask_k() {
    int bx = blockIdx.x, by = blockIdx.y;
    if (bx < by) return;
    __shared__ float4 cb[64];
    int t = threadIdx.x;
    int j0 = bx * 64;
    {
        int j = j0 + t;
        cb[t] = (j < PRE) ? g_sorted[j] : make_float4(0, 0, 0, 0);
    }
    __syncthreads();
    int i = by*64 + t;
    if (i >= PRE) return;
    float4 bi = g_sorted[i];
    float areai = (bi.z - bi.x)*(bi.w - bi.y);
    unsigned long long word = 0;
#pragma unroll 4
    for (int jj = 0; jj < 64; jj++) {
        int j = j0 + jj;
        if (j > i && j < PRE) {
            float4 bj = cb[jj];
            float tly = fmaxf(bi.x, bj.x), tlx = fmaxf(bi.y, bj.y);
            float bry = fminf(bi.z, bj.z), brx = fminf(bi.w, bj.w);
            float hv = fmaxf(bry - tly, 0.f), wv = fmaxf(brx - tlx, 0.f);
            float inter = hv * wv;
            float areaj = (bj.z - bj.x)*(bj.w - bj.y);
            float iou = inter / (areai + areaj - inter + 1e-9f);
            if (iou > 0.7f) word |= (1ull << jj);
        }
    }
    g_mask[(size_t)i*NW + bx] = word;
}

__global__ void nms_reduce_k() {
    __shared__ unsigned long long removed[NW];
    __shared__ unsigned long long kbSh;
    int tid = threadIdx.x;
    for (int i = tid; i < NW; i += blockDim.x) removed[i] = 0;
    __syncthreads();
    for (int c = 0; c < NW; c++) {
        if (tid < 32) {
            int ra = c*64 + tid, rb = ra + 32;
            unsigned long long ia = (ra < PRE) ? g_mask[(size_t)ra*NW + c] : 0ull;
            unsigned long long ib = (rb < PRE) ? g_mask[(size_t)rb*NW + c] : 0ull;
            unsigned long long rw = removed[c];
            unsigned long long kb = 0;
#pragma unroll
            for (int k = 0; k < 32; k++) {
                unsigned long long mk = __shfl_sync(0xffffffffu, ia, k);
                if ((c*64 + k) < PRE && !((rw >> k) & 1ull)) { kb |= (1ull << k); rw |= mk; }
            }
#pragma unroll
            for (int k = 0; k < 32; k++) {
                unsigned long long mk = __shfl_sync(0xffffffffu, ib, k);
                int k2 = k + 32;
                if ((c*64 + k2) < PRE && !((rw >> k2) & 1ull)) { kb |= (1ull << k2); rw |= mk; }
            }
            if (tid == 0) { kbSh = kb; g_keep[c] = kb; }
        }
        __syncthreads();
        unsigned long long kb = kbSh;
        int slots = (NW - 1 - c) * 2;
        for (int slot = tid; slot < slots; slot += blockDim.x) {
            int w  = c + 1 + (slot >> 1);
            int k0 = (slot & 1) * 32;
            unsigned hk = (unsigned)(kb >> k0);
            unsigned long long acc = 0;
            while (hk) {
                int k = __ffs(hk) - 1; hk &= hk - 1;
                acc |= g_mask[(size_t)(c*64 + k0 + k)*NW + w];
            }
            if (acc) atomicOr(&removed[w], acc);
        }
        __syncthreads();
    }
}

__global__ void rois_k(float* __restrict__ out) {
    __shared__ int list[POST];
    __shared__ int nkS;
    if (threadIdx.x == 0) {
        int nk = 0;
        for (int w = 0; w < NW && nk < POST; w++) {
            unsigned long long bits = g_keep[w];
            while (bits && nk < POST) {
                int k = __ffsll(bits) - 1; bits &= bits - 1;
                list[nk++] = w*64 + k;
            }
        }
        nkS = nk;
    }
    __syncthreads();
    int nk = nkS;
    for (int r = threadIdx.x; r < POST; r += blockDim.x) {
        float4 v = make_float4(0, 0, 0, 0);
        if (r < nk) v = g_sorted[list[r]];
        *(float4*)(out + ROI_OFF + r*4) = v;
    }
}

// =====================================================================
extern "C" void kernel_launch(void* const* d_in, const int* in_sizes, int n_in,
                              void* d_out, int out_size) {
    const float* x     = (const float*)d_in[0];
    const float* anch  = (const float*)d_in[1];
    const int*   img   = (const int*)  d_in[2];
    const float* scale = (const float*)d_in[3];
    const float* Wc    = (const float*)d_in[4];
    const float* bc    = (const float*)d_in[5];
    const float* Wsc   = (const float*)d_in[6];
    const float* bsc   = (const float*)d_in[7];
    const float* Wlc   = (const float*)d_in[8];
    const float* blc   = (const float*)d_in[9];
    float* out = (float*)d_out;

    zero_ctrl_k<<<16, 256>>>();
    split_x_k<<<dim3(HH, 4, 32), 256>>>(x);
    split_w_k<<<CMID, 256>>>(Wc);
    build_wh<<<54, 512>>>(Wsc, Wlc);
    cudaFuncSetAttribute(conv_tc, cudaFuncAttributeMaxDynamicSharedMemorySize, SM_BYTES);
    conv_tc<<<dim3(64, 8), 256, SM_BYTES>>>(bc);
    prep_k<<<NANCH/256, 256>>>(anch, img, scale, bsc, blc, out);
    scan1_k<<<1, 32>>>();
    hist2_k<<<NANCH/256, 256>>>();
    scan2_k<<<1, 32>>>();
    compact_k<<<NANCH/256, 256>>>();
    cudaFuncSetAttribute(bitonic_k, cudaFuncAttributeMaxDynamicSharedMemorySize, 8192*8);
    bitonic_k<<<1, 1024, 8192*8>>>();
    mask_k<<<dim3(NW, NW), 64>>>();
    nms_reduce_k<<<1, 256>>>();
    rois_k<<<1, 256>>>(out);
}

// round 7
// speedup vs baseline: 1.4717x; 1.3518x over previous
#include <cuda_runtime.h>
#include <cuda_fp16.h>
#include <cstdint>

#define HH   128
#define WWD  128
#define HWI  (HH*WWD)
#define CIN  1024
#define CMID 512
#define KTOT 9216
#define NANCH (HWI*9)      // 147456
#define PRE  6000
#define POST 300
#define NW   94
#define LOC_OFF (NANCH*2)
#define ROI_OFF (NANCH*6)

// conv_tc smem layout (byte offsets). fp16 tiles.
// X tile: 2 mats x [4 h][130 wc][16 ci + 8 pad] halfs = 2 x 12480 halfs
#define XS_OFF   0
#define XS_MATH  12480            // halfs per mat
#define BS_OFF   49920            // 3 bufs x (2 mats x 64co x 24) halfs
#define BS_BUFH  3072             // halfs per buf
#define BS_MATH  1536
#define WSH_OFF  68352            // 54 x 64 floats
#define BIAS_OFF 82176            // 64 floats
#define SM_BYTES 82432

struct Ctrl { unsigned b1, cAbove1, thresholdKey; int candCount; };

// ---- static device scratch ----
__device__ __align__(16) __half g_Xhi16[CIN*HWI];   // channel-last [p][ci]
__device__ __align__(16) __half g_Xlo16[CIN*HWI];
__device__ __align__(16) __half g_Whi16[CMID*KTOT]; // [co][k], k=(kh*3+kw)*1024+ci
__device__ __align__(16) __half g_Wlo16[CMID*KTOT];
__device__ __align__(16) float g_Wh[54*CMID];
__device__ __align__(16) float g_part[8*HWI*54];    // [cotile][p][o]
__device__ float4 g_boxes4[NANCH];
__device__ unsigned g_key[NANCH];
__device__ unsigned g_hist1[4096];
__device__ unsigned g_hist2[4096];
__device__ unsigned long long g_cand[8192];
__device__ float4 g_sorted[PRE];
__device__ unsigned long long g_mask[(size_t)PRE*NW];
__device__ unsigned long long g_keep[NW];
__device__ Ctrl g_ctrl;

// ================= helpers =================
__device__ __forceinline__ void cpasync16(void* dst, const void* src, int sz) {
    unsigned d = (unsigned)__cvta_generic_to_shared(dst);
    asm volatile("cp.async.cg.shared.global [%0], [%1], 16, %2;\n"
                 :: "r"(d), "l"(src), "r"(sz) : "memory");
}
__device__ __forceinline__ void mma16(float* c, const uint32_t* a, const uint32_t* b) {
    asm volatile("mma.sync.aligned.m16n8k16.row.col.f32.f16.f16.f32 "
        "{%0,%1,%2,%3}, {%4,%5,%6,%7}, {%8,%9}, {%0,%1,%2,%3};"
        : "+f"(c[0]), "+f"(c[1]), "+f"(c[2]), "+f"(c[3])
        : "r"(a[0]), "r"(a[1]), "r"(a[2]), "r"(a[3]), "r"(b[0]), "r"(b[1]));
}
__device__ __forceinline__ void h_split(float x, __half& hi, __half& lo) {
    hi = __float2half_rn(x);
    lo = __float2half_rn(x - __half2float(hi));
}

// ================= prep kernels =================
__global__ void zero_ctrl_k() {
    int t = blockIdx.x*blockDim.x + threadIdx.x;
    if (t < 4096) { g_hist1[t] = 0; g_hist2[t] = 0; }
    if (t == 0) { g_ctrl.candCount = 0; g_ctrl.b1 = 0; g_ctrl.cAbove1 = 0; g_ctrl.thresholdKey = 0; }
}

// X [ci][h][w] -> channel-last hi/lo halfs [p][ci]
__global__ void split_x_k(const float* __restrict__ X) {
    __shared__ float t[32][33];
    int h = blockIdx.x, w0 = blockIdx.y << 5, c0 = blockIdx.z << 5;
    int tid = threadIdx.x;
#pragma unroll
    for (int it = 0; it < 4; it++) {
        int idx = tid + it*256;
        int ci = idx >> 5, w = idx & 31;
        t[ci][w] = X[(c0 + ci)*HWI + h*WWD + w0 + w];
    }
    __syncthreads();
#pragma unroll
    for (int it = 0; it < 4; it++) {
        int idx = tid + it*256;
        int w = idx >> 5, ci = idx & 31;
        __half hi, lo;
        h_split(t[ci][w], hi, lo);
        size_t off = ((size_t)(h*WWD + w0 + w) << 10) + c0 + ci;
        g_Xhi16[off] = hi; g_Xlo16[off] = lo;
    }
}

// W [co][ci][3][3] -> hi/lo halfs [co][k], k=(kh*3+kw)*1024+ci
__global__ void split_w_k(const float* __restrict__ Wc) {
    int co = blockIdx.x;
    for (int k = threadIdx.x; k < KTOT; k += blockDim.x) {
        int g = k >> 10, ci = k & 1023;
        float v = Wc[((size_t)co*CIN + ci)*9 + g];
        __half hi, lo;
        h_split(v, hi, lo);
        g_Whi16[(size_t)co*KTOT + k] = hi;
        g_Wlo16[(size_t)co*KTOT + k] = lo;
    }
}

__global__ void build_wh(const float* __restrict__ Wsc, const float* __restrict__ Wlc) {
    int idx = blockIdx.x*blockDim.x + threadIdx.x;  // 54*512
    int o = idx >> 9;
    g_Wh[idx] = (o < 18) ? Wsc[idx] : Wlc[idx - 18*CMID];
}

// =====================================================================
// conv 3x3 1024->512 via mma.sync m16n8k16 fp16 pair-split (3 terms),
// RZ-safe: acc_hh flushed to fp32 acc_sum per 16-ci chunk; acc_x small.
// CTA: 256 pos (2 rows) x 64 co; 8 warps (4m x 2n), warp tile 64x32
// =====================================================================
__global__ void __launch_bounds__(256, 1)
conv_tc(const float* __restrict__ bconv) {
    extern __shared__ __align__(16) char smem[];
    __half* Xs = (__half*)(smem + XS_OFF);
    __half* Bs = (__half*)(smem + BS_OFF);
    float* Wsh = (float*)(smem + WSH_OFF);
    float* bias_sh = (float*)(smem + BIAS_OFF);
    const int tid = threadIdx.x, lane = tid & 31, wid = tid >> 5;
    const int g8 = lane >> 2, t4 = lane & 3;
    const int wm = wid & 3, wn = wid >> 2;     // warp grid 4(m) x 2(n)
    const int bt = blockIdx.x, coTile = blockIdx.y;
    const int coBase = coTile << 6;
    const int hBase = bt << 1;

    for (int i = tid; i < 54*64; i += 256)
        Wsh[i] = g_Wh[(i >> 6)*CMID + coBase + (i & 63)];
    if (tid < 64) bias_sh[tid] = bconv[coBase + tid];

    // per-thread fragment base offsets (halfs)
    int bA[4];
#pragma unroll
    for (int mi = 0; mi < 4; mi++) {
        int p0 = wm*64 + mi*16 + g8;
        bA[mi] = (p0 >> 7)*3120 + (p0 & 127)*24 + 2*t4;
    }
    int bB[4];
#pragma unroll
    for (int ni = 0; ni < 4; ni++)
        bB[ni] = (wn*32 + ni*8 + g8)*24 + 2*t4;

    float acc_hh[4][4][4], acc_x[4][4][4], acc_sum[4][4][4];
#pragma unroll
    for (int mi = 0; mi < 4; mi++)
#pragma unroll
        for (int ni = 0; ni < 4; ni++)
#pragma unroll
            for (int q = 0; q < 4; q++) {
                acc_hh[mi][ni][q] = 0.f; acc_x[mi][ni][q] = 0.f; acc_sum[mi][ni][q] = 0.f;
            }

    for (int ch = 0; ch < 64; ch++) {
        const int ci0 = ch << 4;
        __syncthreads();    // Xs + all B bufs free
        // ---- stage X tile: 2 mats x 4 h x 130 wc x 16 ci (16B units) ----
        for (int idx = tid; idx < 2080; idx += 256) {
            int mat = (idx >= 1040) ? 1 : 0;
            int rem = idx - mat*1040;
            int h = rem/260, sub = rem - h*260;
            int wc = sub >> 1, seg = sub & 1;
            int hp = hBase + h - 1, wp = wc - 1;
            bool ok = ((unsigned)hp < 128u) && ((unsigned)wp < 128u);
            const __half* src = (mat ? g_Xlo16 : g_Xhi16)
                + (((size_t)((hp & 127)*WWD + (wp & 127))) << 10) + ci0 + (seg << 3);
            cpasync16(Xs + mat*XS_MATH + h*3120 + wc*24 + (seg << 3), src, ok ? 16 : 0);
        }
        asm volatile("cp.async.commit_group;" ::: "memory");
        // ---- stage B for tap g=0 (buf 0) ----
        {
            int mat = tid >> 7, co = (tid >> 1) & 63, seg = tid & 1;
            const __half* src = (mat ? g_Wlo16 : g_Whi16)
                + (size_t)(coBase + co)*KTOT + ci0 + (seg << 3);
            cpasync16(Bs + mat*BS_MATH + co*24 + (seg << 3), src, 16);
            asm volatile("cp.async.commit_group;" ::: "memory");
        }

        for (int g = 0; g < 9; g++) {
            if (g + 1 < 9) {       // stage next tap into buf (g+1)%3
                int nb = (g + 1) % 3;
                int mat = tid >> 7, co = (tid >> 1) & 63, seg = tid & 1;
                const __half* src = (mat ? g_Wlo16 : g_Whi16)
                    + (size_t)(coBase + co)*KTOT + ((g + 1) << 10) + ci0 + (seg << 3);
                cpasync16(Bs + nb*BS_BUFH + mat*BS_MATH + co*24 + (seg << 3), src, 16);
                asm volatile("cp.async.commit_group;" ::: "memory");
                asm volatile("cp.async.wait_group 1;" ::: "memory");
            } else {
                asm volatile("cp.async.wait_group 0;" ::: "memory");
            }
            __syncthreads();

            const int kh = g / 3, kw = g - kh*3;
            const int aoff = kh*3120 + kw*24;
            const __half* Bb = Bs + (g % 3)*BS_BUFH;

            uint32_t bh[4][2], bl[4][2];
#pragma unroll
            for (int ni = 0; ni < 4; ni++) {
                bh[ni][0] = *(const uint32_t*)(Bb + bB[ni]);
                bh[ni][1] = *(const uint32_t*)(Bb + bB[ni] + 8);
                bl[ni][0] = *(const uint32_t*)(Bb + BS_MATH + bB[ni]);
                bl[ni][1] = *(const uint32_t*)(Bb + BS_MATH + bB[ni] + 8);
            }
#pragma unroll
            for (int mi = 0; mi < 4; mi++) {
                int ab = bA[mi] + aoff;
                uint32_t ah[4], al[4];
                ah[0] = *(const uint32_t*)(Xs + ab);
                ah[1] = *(const uint32_t*)(Xs + ab + 192);
                ah[2] = *(const uint32_t*)(Xs + ab + 8);
                ah[3] = *(const uint32_t*)(Xs + ab + 200);
                al[0] = *(const uint32_t*)(Xs + XS_MATH + ab);
                al[1] = *(const uint32_t*)(Xs + XS_MATH + ab + 192);
                al[2] = *(const uint32_t*)(Xs + XS_MATH + ab + 8);
                al[3] = *(const uint32_t*)(Xs + XS_MATH + ab + 200);
#pragma unroll
                for (int ni = 0; ni < 4; ni++) {
                    mma16(acc_hh[mi][ni], ah, bh[ni]);
                    mma16(acc_x[mi][ni], ah, bl[ni]);
                    mma16(acc_x[mi][ni], al, bh[ni]);
                }
            }
        }
        // ---- flush hi*hi window into RN fp32 accumulator ----
#pragma unroll
        for (int mi = 0; mi < 4; mi++)
#pragma unroll
            for (int ni = 0; ni < 4; ni++)
#pragma unroll
                for (int q = 0; q < 4; q++) {
                    acc_sum[mi][ni][q] += acc_hh[mi][ni][q];
                    acc_hh[mi][ni][q] = 0.f;
                }
    }
    __syncthreads();

    // ---- epilogue: feat tile (64co x 256p) floats, aliases X/B tiles ----
    float* Sfeat = (float*)smem;   // [64][260]
#pragma unroll
    for (int mi = 0; mi < 4; mi++) {
        int p0 = wm*64 + mi*16 + g8;
#pragma unroll
        for (int ni = 0; ni < 4; ni++) {
            int co = wn*32 + ni*8 + (t4 << 1);
            float v0 = acc_sum[mi][ni][0] + acc_x[mi][ni][0] + bias_sh[co];
            float v1 = acc_sum[mi][ni][1] + acc_x[mi][ni][1] + bias_sh[co + 1];
            float v2 = acc_sum[mi][ni][2] + acc_x[mi][ni][2] + bias_sh[co];
            float v3 = acc_sum[mi][ni][3] + acc_x[mi][ni][3] + bias_sh[co + 1];
            Sfeat[co*260 + p0]           = fmaxf(v0, 0.f);
            Sfeat[(co + 1)*260 + p0]     = fmaxf(v1, 0.f);
            Sfeat[co*260 + p0 + 8]       = fmaxf(v2, 0.f);
            Sfeat[(co + 1)*260 + p0 + 8] = fmaxf(v3, 0.f);
        }
    }
    __syncthreads();

    // ---- head partials: 54 outs over this co-tile's 64 channels ----
    {
        int pl = tid;
        float a54[54];
#pragma unroll
        for (int o = 0; o < 54; o++) a54[o] = 0.f;
        for (int co = 0; co < 64; co++) {
            float f = Sfeat[co*260 + pl];
#pragma unroll
            for (int o = 0; o < 54; o++)
                a54[o] = fmaf(f, Wsh[o*64 + co], a54[o]);
        }
        float* dst = g_part + ((size_t)coTile*HWI + bt*256 + pl)*54;
#pragma unroll
        for (int o = 0; o < 54; o++) dst[o] = a54[o];
    }
}

// ================= proposal pipeline (exact) =================
__global__ void prep_k(const float* __restrict__ anch,
                       const int* __restrict__ img, const float* __restrict__ scale,
                       const float* __restrict__ bsc, const float* __restrict__ blc,
                       float* __restrict__ out) {
    __shared__ unsigned sh[4096];
    for (int i = threadIdx.x; i < 4096; i += blockDim.x) sh[i] = 0;
    __syncthreads();
    int i = blockIdx.x*blockDim.x + threadIdx.x;
    {
        int p = i / 9, a = i - p*9;
        float s0 = bsc[2*a], s1 = bsc[2*a + 1];
        float dy = blc[4*a], dx = blc[4*a+1], dh = blc[4*a+2], dw = blc[4*a+3];
#pragma unroll
        for (int t = 0; t < 8; t++) {
            const float* pp = g_part + ((size_t)t*HWI + p)*54;
            s0 += pp[2*a];      s1 += pp[2*a + 1];
            dy += pp[18 + 4*a]; dx += pp[18 + 4*a + 1];
            dh += pp[18 + 4*a + 2]; dw += pp[18 + 4*a + 3];
        }
        out[p*18 + 2*a]     = s0;
        out[p*18 + 2*a + 1] = s1;
        float* lo = out + LOC_OFF + p*36 + 4*a;
        lo[0] = dy; lo[1] = dx; lo[2] = dh; lo[3] = dw;

        float m = fmaxf(s0, s1);
        float e0 = expf(s0 - m), e1 = expf(s1 - m);
        float fg = e1 / (e0 + e1);
        float ay1 = anch[i*4], ax1 = anch[i*4+1], ay2 = anch[i*4+2], ax2 = anch[i*4+3];
        float ahh = ay2 - ay1, aww = ax2 - ax1;
        float acy = ay1 + 0.5f*ahh, acx = ax1 + 0.5f*aww;
        float cy = dy*ahh + acy, cx = dx*aww + acx;
        float bh = expf(dh)*ahh, bw = expf(dw)*aww;
        float imh = (float)img[0], imw = (float)img[1];
        float y1 = fminf(fmaxf(cy - 0.5f*bh, 0.f), imh);
        float x1 = fminf(fmaxf(cx - 0.5f*bw, 0.f), imw);
        float y2 = fminf(fmaxf(cy + 0.5f*bh, 0.f), imh);
        float x2 = fminf(fmaxf(cx + 0.5f*bw, 0.f), imw);
        g_boxes4[i] = make_float4(y1, x1, y2, x2);
        float ms = 16.0f * scale[0];
        bool valid = ((y2 - y1) >= ms) && ((x2 - x1) >= ms);
        float sc = valid ? fg : -1e9f;
        unsigned u = __float_as_uint(sc);
        u = (u & 0x80000000u) ? ~u : (u | 0x80000000u);
        g_key[i] = u;
        atomicAdd(&sh[u >> 20], 1u);
    }
    __syncthreads();
    for (int b = threadIdx.x; b < 4096; b += blockDim.x)
        if (sh[b]) atomicAdd(&g_hist1[b], sh[b]);
}

__global__ void scan1_k() {
    __shared__ unsigned seg[32];
    int t = threadIdx.x;
    unsigned s = 0;
    for (int b = 0; b < 128; b++) s += g_hist1[t*128 + b];
    seg[t] = s;
    __syncwarp();
    if (t == 0) {
        unsigned target = PRE, cum = 0; int si = 31;
        for (; si >= 0; si--) { if (cum + seg[si] >= target) break; cum += seg[si]; }
        if (si < 0) si = 0;
        unsigned c2 = cum; unsigned b1 = si*128;
        for (int b = si*128 + 127; b >= si*128; b--) {
            unsigned hv = g_hist1[b];
            if (c2 + hv >= target) { b1 = b; break; }
            c2 += hv;
        }
        g_ctrl.b1 = b1; g_ctrl.cAbove1 = c2;
    }
}

__global__ void hist2_k() {
    int i = blockIdx.x*blockDim.x + threadIdx.x;
    unsigned u = g_key[i];
    if ((u >> 20) == g_ctrl.b1) atomicAdd(&g_hist2[(u >> 8) & 0xFFFu], 1u);
}

__global__ void scan2_k() {
    __shared__ unsigned seg[32];
    int t = threadIdx.x;
    unsigned s = 0;
    for (int b = 0; b < 128; b++) s += g_hist2[t*128 + b];
    seg[t] = s;
    __syncwarp();
    if (t == 0) {
        unsigned target = PRE - g_ctrl.cAbove1, cum = 0; int si = 31;
        for (; si >= 0; si--) { if (cum + seg[si] >= target) break; cum += seg[si]; }
        if (si < 0) si = 0;
        unsigned c2 = cum; unsigned b2 = si*128;
        for (int b = si*128 + 127; b >= si*128; b--) {
            unsigned hv = g_hist2[b];
            if (c2 + hv >= target) { b2 = b; break; }
            c2 += hv;
        }
        g_ctrl.thresholdKey = (g_ctrl.b1 << 20) | (b2 << 8);
    }
}

__global__ void compact_k() {
    int i = blockIdx.x*blockDim.x + threadIdx.x;
    unsigned u = g_key[i];
    if (u >= g_ctrl.thresholdKey) {
        int pos = atomicAdd(&g_ctrl.candCount, 1);
        if (pos < 8192)
            g_cand[pos] = ((unsigned long long)(~u) << 32) | (unsigned)i;
    }
}

__global__ void bitonic_k() {
    extern __shared__ unsigned long long shm[];
    int tid = threadIdx.x;
    int n = g_ctrl.candCount; if (n > 8192) n = 8192;
    for (int i = tid; i < 8192; i += 1024)
        shm[i] = (i < n) ? g_cand[i] : 0xFFFFFFFFFFFFFFFFull;
    __syncthreads();
    for (int k = 2; k <= 8192; k <<= 1) {
        for (int j = k >> 1; j > 0; j >>= 1) {
            for (int e = tid; e < 8192; e += 1024) {
                int p = e ^ j;
                if (p > e) {
                    unsigned long long a = shm[e], b = shm[p];
                    bool up = ((e & k) == 0);
                    if (up ? (a > b) : (a < b)) { shm[e] = b; shm[p] = a; }
                }
            }
            __syncthreads();
        }
    }
    for (int r = tid; r < PRE; r += 1024) {
        unsigned idx = (unsigned)shm[r];
        g_sorted[r] = g_boxes4[idx];
    }
}

__global__ void mask_k() {
    int bx = blockIdx.x, by = blockIdx.y;
    if (bx < by) return;
    __shared__ float4 cb[64];
    int t = threadIdx.x;
    int j0 = bx * 64;
    {
        int j = j0 + t;
        cb[t] = (j < PRE) ? g_sorted[j] : make_float4(0, 0, 0, 0);
    }
    __syncthreads();
    int i = by*64 + t;
    if (i >= PRE) return;
    float4 bi = g_sorted[i];
    float areai = (bi.z - bi.x)*(bi.w - bi.y);
    unsigned long long word = 0;
#pragma unroll 4
    for (int jj = 0; jj < 64; jj++) {
        int j = j0 + jj;
        if (j > i && j < PRE) {
            float4 bj = cb[jj];
            float tly = fmaxf(bi.x, bj.x), tlx = fmaxf(bi.y, bj.y);
            float bry = fminf(bi.z, bj.z), brx = fminf(bi.w, bj.w);
            float hv = fmaxf(bry - tly, 0.f), wv = fmaxf(brx - tlx, 0.f);
            float inter = hv * wv;
            float areaj = (bj.z - bj.x)*(bj.w - bj.y);
            float iou = inter / (areai + areaj - inter + 1e-9f);
            if (iou > 0.7f) word |= (1ull << jj);
        }
    }
    g_mask[(size_t)i*NW + bx] = word;
}

__global__ void nms_reduce_k() {
    __shared__ unsigned long long removed[NW];
    __shared__ unsigned long long kbSh;
    int tid = threadIdx.x;
    for (int i = tid; i < NW; i += blockDim.x) removed[i] = 0;
    __syncthreads();
    for (int c = 0; c < NW; c++) {
        if (tid < 32) {
            int ra = c*64 + tid, rb = ra + 32;
            unsigned long long ia = (ra < PRE) ? g_mask[(size_t)ra*NW + c] : 0ull;
            unsigned long long ib = (rb < PRE) ? g_mask[(size_t)rb*NW + c] : 0ull;
            unsigned long long rw = removed[c];
            unsigned long long kb = 0;
#pragma unroll
            for (int k = 0; k < 32; k++) {
                unsigned long long mk = __shfl_sync(0xffffffffu, ia, k);
                if ((c*64 + k) < PRE && !((rw >> k) & 1ull)) { kb |= (1ull << k); rw |= mk; }
            }
#pragma unroll
            for (int k = 0; k < 32; k++) {
                unsigned long long mk = __shfl_sync(0xffffffffu, ib, k);
                int k2 = k + 32;
                if ((c*64 + k2) < PRE && !((rw >> k2) & 1ull)) { kb |= (1ull << k2); rw |= mk; }
            }
            if (tid == 0) { kbSh = kb; g_keep[c] = kb; }
        }
        __syncthreads();
        unsigned long long kb = kbSh;
        int slots = (NW - 1 - c) * 2;
        for (int slot = tid; slot < slots; slot += blockDim.x) {
            int w  = c + 1 + (slot >> 1);
            int k0 = (slot & 1) * 32;
            unsigned hk = (unsigned)(kb >> k0);
            unsigned long long acc = 0;
            while (hk) {
                int k = __ffs(hk) - 1; hk &= hk - 1;
                acc |= g_mask[(size_t)(c*64 + k0 + k)*NW + w];
            }
            if (acc) atomicOr(&removed[w], acc);
        }
        __syncthreads();
    }
}

__global__ void rois_k(float* __restrict__ out) {
    __shared__ int list[POST];
    __shared__ int nkS;
    if (threadIdx.x == 0) {
        int nk = 0;
        for (int w = 0; w < NW && nk < POST; w++) {
            unsigned long long bits = g_keep[w];
            while (bits && nk < POST) {
                int k = __ffsll(bits) - 1; bits &= bits - 1;
                list[nk++] = w*64 + k;
            }
        }
        nkS = nk;
    }
    __syncthreads();
    int nk = nkS;
    for (int r = threadIdx.x; r < POST; r += blockDim.x) {
        float4 v = make_float4(0, 0, 0, 0);
        if (r < nk) v = g_sorted[list[r]];
        *(float4*)(out + ROI_OFF + r*4) = v;
    }
}

// =====================================================================
extern "C" void kernel_launch(void* const* d_in, const int* in_sizes, int n_in,
                              void* d_out, int out_size) {
    const float* x     = (const float*)d_in[0];
    const float* anch  = (const float*)d_in[1];
    const int*   img   = (const int*)  d_in[2];
    const float* scale = (const float*)d_in[3];
    const float* Wc    = (const float*)d_in[4];
    const float* bc    = (const float*)d_in[5];
    const float* Wsc   = (const float*)d_in[6];
    const float* bsc   = (const float*)d_in[7];
    const float* Wlc   = (const float*)d_in[8];
    const float* blc   = (const float*)d_in[9];
    float* out = (float*)d_out;

    zero_ctrl_k<<<16, 256>>>();
    split_x_k<<<dim3(HH, 4, 32), 256>>>(x);
    split_w_k<<<CMID, 256>>>(Wc);
    build_wh<<<54, 512>>>(Wsc, Wlc);
    cudaFuncSetAttribute(conv_tc, cudaFuncAttributeMaxDynamicSharedMemorySize, SM_BYTES);
    conv_tc<<<dim3(64, 8), 256, SM_BYTES>>>(bc);
    prep_k<<<NANCH/256, 256>>>(anch, img, scale, bsc, blc, out);
    scan1_k<<<1, 32>>>();
    hist2_k<<<NANCH/256, 256>>>();
    scan2_k<<<1, 32>>>();
    compact_k<<<NANCH/256, 256>>>();
    cudaFuncSetAttribute(bitonic_k, cudaFuncAttributeMaxDynamicSharedMemorySize, 8192*8);
    bitonic_k<<<1, 1024, 8192*8>>>();
    mask_k<<<dim3(NW, NW), 64>>>();
    nms_reduce_k<<<1, 256>>>();
    rois_k<<<1, 256>>>(out);
}